// round 16
// baseline (speedup 1.0000x reference)
#include <cuda_runtime.h>
#include <cuda_bf16.h>
#include <math.h>
#include <stdint.h>

// Problem dims
#define B_  64
#define N_  16
#define T_  64
#define D_  128
#define H_  256
#define M_  17          // N+1 slots
#define RALL 1088       // B + B*N batch rows
#define FLATR 69632     // RALL*T  (also B*M_*T_)
#define NBLK 136        // persistent GRU blocks (8 j-tiles x 17 m-tiles)
#define NHELP 12        // helper blocks (Wfull chain; first 8 also do Q2)
#define GRID_GRU (NBLK + NHELP)

// Output offsets (concat of: out(4096), node_hT(16384), ngh_hT(262144), A(4456448))
#define OFF_OUT 0
#define OFF_NHT 4096
#define OFF_GHT 20480
#define OFF_A   282624

// gru smem layout (words)
#define WSTR 264                          // fragment-pair stride per row
#define GRU_WS_WORDS (96 * WSTR)
#define GRU_HS_WORDS (64 * WSTR)
#define GRU_GH_WORDS (64 * 100)
#define GRU_SMEM_WORDS (GRU_WS_WORDS + GRU_HS_WORDS + GRU_GH_WORDS)

// gemm_xw pipeline smem (words): chunk stride 40 (mod32=8 -> conflict-free LDS.64)
#define XW_CHUNK 40
#define XW_MAT   (128 * XW_CHUNK)
#define XW_SMEM_WORDS (4 * XW_MAT)        // As0, As1, Bs0, Bs1

// conv grid split
#define CONV_X_ITEMS (FLATR * 16)        // 8 words per item
#define CONV_W_ITEMS (768 * 16)
#define CONVB ((CONV_X_ITEMS + 2 * CONV_W_ITEMS) / 256)   // 4448

// ---------------- device scratch (no runtime allocation allowed) ----------------
__device__ float    g_gi[(size_t)FLATR * 768];   // precomputed x@Wih.T, [(r*T+t)*768+j]
__device__ uint32_t g_xt[(size_t)FLATR * 128];   // tf32 pre-permuted X (node rows first)
__device__ uint32_t g_wt[2 * 768 * 128];         // tf32 pre-permuted Wih (node, ngh)
__device__ float    g_h0[RALL * H_];             // fp32 initial h
__device__ uint32_t g_hx0[RALL * H_];            // tf32 exchange ping (perm8 order)
__device__ uint32_t g_hx1[RALL * H_];            // tf32 exchange pong (perm8 order)
__device__ float    g_hall[(size_t)FLATR * H_];  // kv layout [((b*17+m)*64+t)*256+h]
__device__ float    g_Q2[(size_t)B_ * T_ * H_];
__device__ float    g_tmp[H_ * H_];              // Wq^T @ Wbil
__device__ float    g_WfullT[H_ * H_];           // (Wq^T Wbil Wk) transposed
__device__ float    g_wvc[H_];                   // Wprj @ Wv
__device__ float    g_vp[8 * FLATR];             // per-jt partial hall.wvc
__device__ float    g_po[B_ * M_ * T_];          // per-slot partial output
__device__ unsigned g_barm[M_ * 32];             // per-m-tile barrier counters, 128B apart
__device__ unsigned g_barh;                      // helper-phase barrier counter
__device__ unsigned g_barq;                      // node hall[t] readiness counter

// ---------------- helpers ----------------
__device__ __forceinline__ uint32_t f2tf32(float f) {
    uint32_t o;
    asm("cvt.rna.tf32.f32 %0, %1;" : "=r"(o) : "f"(f));
    return o;
}

__device__ __forceinline__ void mma_tf32(float& d0, float& d1, float& d2, float& d3,
                                         uint32_t a0, uint32_t a1, uint32_t a2, uint32_t a3,
                                         uint32_t b0, uint32_t b1) {
    asm volatile(
        "mma.sync.aligned.m16n8k8.row.col.f32.tf32.tf32.f32 "
        "{%0,%1,%2,%3}, {%4,%5,%6,%7}, {%8,%9}, {%0,%1,%2,%3};\n"
        : "+f"(d0), "+f"(d1), "+f"(d2), "+f"(d3)
        : "r"(a0), "r"(a1), "r"(a2), "r"(a3), "r"(b0), "r"(b1));
}

__device__ __forceinline__ float fsigmoid(float x) {
    return __fdividef(1.f, 1.f + __expf(-x));
}
__device__ __forceinline__ float ftanh(float x) {
    return 1.f - __fdividef(2.f, 1.f + __expf(2.f * x));
}

__device__ __forceinline__ void cp_async16(uint32_t dst, const void* src) {
    asm volatile("cp.async.ca.shared.global [%0], [%1], 16;" :: "r"(dst), "l"(src));
}
__device__ __forceinline__ void cp_async16_cg(uint32_t dst, const void* src) {
    asm volatile("cp.async.cg.shared.global [%0], [%1], 16;" :: "r"(dst), "l"(src));
}
__device__ __forceinline__ void cp_commit() {
    asm volatile("cp.async.commit_group;" ::: "memory");
}
template <int N>
__device__ __forceinline__ void cp_wait() {
    asm volatile("cp.async.wait_group %0;" :: "n"(N) : "memory");
}

__device__ __forceinline__ void bar_arrive(unsigned* p) {
    asm volatile("red.release.gpu.add.u32 [%0], %1;" :: "l"(p), "r"(1u) : "memory");
}
__device__ __forceinline__ void bar_wait(unsigned* p, unsigned target) {
    unsigned v;
    do {
        asm volatile("ld.acquire.gpu.u32 %0, [%1];" : "=r"(v) : "l"(p) : "memory");
    } while (v < target);
}

// fragment-pair permutation within an 8-word k-group
__device__ __forceinline__ int perm8(int k) {
    return ((k & 3) << 1) | ((k >> 2) & 1);
}

// permute 8 consecutive k-words into fragment-pair order + tf32 convert
__device__ __forceinline__ void conv_pack8(const float* __restrict__ src,
                                           uint32_t* __restrict__ dst) {
    float4 v0 = *(const float4*)(src);
    float4 v1 = *(const float4*)(src + 4);
    *(uint4*)(dst)     = make_uint4(f2tf32(v0.x), f2tf32(v1.x), f2tf32(v0.y), f2tf32(v1.y));
    *(uint4*)(dst + 4) = make_uint4(f2tf32(v0.z), f2tf32(v1.z), f2tf32(v0.w), f2tf32(v1.w));
}

// ---------------- fused pass: conv(X,Wih) + init_h + wvc + barrier resets --------
__global__ void conv_all(const float* __restrict__ node_input,
                         const float* __restrict__ ngh_input,
                         const float* __restrict__ Wih_node,
                         const float* __restrict__ Wih_ngh,
                         const float* __restrict__ node_hidden,
                         const float* __restrict__ ngh_hidden,
                         const float* __restrict__ Wprj, const float* __restrict__ Wv,
                         uint32_t* __restrict__ xt, uint32_t* __restrict__ wt,
                         float* __restrict__ h, uint32_t* __restrict__ hx,
                         float* __restrict__ wvc) {
    int bx = blockIdx.x;
    if (bx < CONVB) {
        int idx = bx * 256 + threadIdx.x;
        if (idx < CONV_X_ITEMS) {
            size_t off = (size_t)idx * 8;
            const float* src = (off < (size_t)4096 * 128)
                             ? node_input + off
                             : ngh_input + (off - (size_t)4096 * 128);
            conv_pack8(src, xt + off);
        } else {
            int w = idx - CONV_X_ITEMS;
            size_t off = (size_t)(w % CONV_W_ITEMS) * 8;
            const float* src = (w < CONV_W_ITEMS) ? Wih_node + off : Wih_ngh + off;
            conv_pack8(src, wt + (w < CONV_W_ITEMS ? 0 : 768 * 128) + off);
        }
    } else if (bx < CONVB + RALL) {
        int row = bx - CONVB, u = threadIdx.x;
        float v = (row < B_) ? node_hidden[row * H_ + u]
                             : ngh_hidden[(row - B_) * H_ + u];
        h[row * H_ + u] = v;
        hx[row * H_ + (u & ~7) + perm8(u & 7)] = f2tf32(v);
    } else {
        int hp = threadIdx.x;
        float acc[8] = {};
        for (int h0 = 0; h0 < H_; h0 += 8) {
            #pragma unroll
            for (int u = 0; u < 8; u++)
                acc[u] += Wprj[h0 + u] * Wv[(size_t)(h0 + u) * H_ + hp];
        }
        wvc[hp] = ((acc[0] + acc[1]) + (acc[2] + acc[3])) +
                  ((acc[4] + acc[5]) + (acc[6] + acc[7]));
        if (hp < M_) g_barm[hp * 32] = 0;   // reset every launch/replay
        if (hp == 32) g_barh = 0;
        if (hp == 33) g_barq = 0;
    }
}

// ---------------- helper tile bodies (identical math to prior prep kernels) ------
__device__ void tmp_tile(const float* __restrict__ Wq, const float* __restrict__ Wbil,
                         float* __restrict__ tmp, float* As, float* Bs,
                         int k0, int c0) {
    int tid = threadIdx.x, tx = tid & 15, ty = tid >> 4;
    float acc[4][4] = {};
    for (int a0 = 0; a0 < H_; a0 += 16) {
        #pragma unroll
        for (int i = tid; i < 1024; i += 256) {
            int a = i >> 6, q = i & 63;
            As[a * 68 + q] = Wq[(size_t)(a0 + a) * H_ + k0 + q];
            Bs[a * 68 + q] = Wbil[(size_t)(a0 + a) * H_ + c0 + q];
        }
        __syncthreads();
        #pragma unroll
        for (int a = 0; a < 16; a++) {
            float4 av = *(const float4*)&As[a * 68 + ty * 4];
            float4 bv = *(const float4*)&Bs[a * 68 + tx * 4];
            float aa[4] = { av.x, av.y, av.z, av.w };
            float bb[4] = { bv.x, bv.y, bv.z, bv.w };
            #pragma unroll
            for (int i = 0; i < 4; i++)
                #pragma unroll
                for (int j = 0; j < 4; j++) acc[i][j] += aa[i] * bb[j];
        }
        __syncthreads();
    }
    #pragma unroll
    for (int i = 0; i < 4; i++)
        *(float4*)&tmp[(size_t)(k0 + ty * 4 + i) * H_ + c0 + tx * 4] =
            make_float4(acc[i][0], acc[i][1], acc[i][2], acc[i][3]);
}

__device__ void wfull_tile(const float* __restrict__ tmp, const float* __restrict__ Wk,
                           float* __restrict__ WfullT, float* As, float* Bs,
                           int k0, int hp0) {
    int tid = threadIdx.x, tx = tid & 15, ty = tid >> 4;
    float acc[4][4] = {};
    for (int c0 = 0; c0 < H_; c0 += 16) {
        #pragma unroll
        for (int i = tid; i < 1024; i += 256) {
            int r = i >> 4, c = i & 15;
            As[c * 68 + r] = tmp[(size_t)(k0 + r) * H_ + c0 + c];
        }
        #pragma unroll
        for (int i = tid; i < 1024; i += 256) {
            int c = i >> 6, q = i & 63;
            Bs[c * 68 + q] = Wk[(size_t)(c0 + c) * H_ + hp0 + q];
        }
        __syncthreads();
        #pragma unroll
        for (int c = 0; c < 16; c++) {
            float4 hv = *(const float4*)&Bs[c * 68 + ty * 4];
            float4 kv = *(const float4*)&As[c * 68 + tx * 4];
            float hh[4] = { hv.x, hv.y, hv.z, hv.w };
            float kk[4] = { kv.x, kv.y, kv.z, kv.w };
            #pragma unroll
            for (int i = 0; i < 4; i++)
                #pragma unroll
                for (int j = 0; j < 4; j++) acc[i][j] += hh[i] * kk[j];
        }
        __syncthreads();
    }
    #pragma unroll
    for (int i = 0; i < 4; i++)
        *(float4*)&WfullT[(size_t)(hp0 + ty * 4 + i) * H_ + k0 + tx * 4] =
            make_float4(acc[i][0], acc[i][1], acc[i][2], acc[i][3]);
}

// ---------------- pipelined tf32 GEMM on pre-converted operands ----------------
__global__ __launch_bounds__(256, 2) void gemm_xw(const uint32_t* __restrict__ X,
                                                  const uint32_t* __restrict__ W,
                                                  float* __restrict__ C) {
    extern __shared__ uint32_t xsh[];
    uint32_t sbase = (uint32_t)__cvta_generic_to_shared(xsh);
    int tid = threadIdx.x;
    int warp = tid >> 5, lane = tid & 31;
    int gr = lane >> 2, gc = lane & 3;
    int m0 = blockIdx.y * 128, n0 = blockIdx.x * 128;
    int wm = (warp >> 2) * 64, wn = (warp & 3) * 32;

    auto load_chunk = [&](int c, int p) {
        uint32_t abase = sbase + (uint32_t)(p * XW_MAT) * 4u;
        uint32_t bbase = sbase + (uint32_t)((2 + p) * XW_MAT) * 4u;
        #pragma unroll
        for (int s = 0; s < 4; s++) {
            int q = tid + s * 256;
            int row = q >> 3, seg = q & 7;
            uint32_t off = (uint32_t)(row * XW_CHUNK + seg * 4) * 4u;
            cp_async16(abase + off, X + (size_t)(m0 + row) * 128 + c * 32 + seg * 4);
            cp_async16(bbase + off, W + (size_t)(n0 + row) * 128 + c * 32 + seg * 4);
        }
        cp_commit();
    };

    float acc[4][4][4] = {};
    load_chunk(0, 0);

    for (int c = 0; c < 4; c++) {
        if (c < 3) { load_chunk(c + 1, (c + 1) & 1); cp_wait<1>(); }
        else       { cp_wait<0>(); }
        __syncthreads();

        const uint32_t* As = xsh + (c & 1) * XW_MAT;
        const uint32_t* Bs = xsh + (2 + (c & 1)) * XW_MAT;

        #pragma unroll
        for (int kk = 0; kk < 4; kk++) {
            int kb = kk * 8 + gc * 2;
            uint2 a[4][2];
            #pragma unroll
            for (int mt = 0; mt < 4; mt++) {
                int r = wm + mt * 16 + gr;
                a[mt][0] = *(const uint2*)(As + r * XW_CHUNK + kb);
                a[mt][1] = *(const uint2*)(As + (r + 8) * XW_CHUNK + kb);
            }
            uint2 b[4];
            #pragma unroll
            for (int nt = 0; nt < 4; nt++) {
                int n = wn + nt * 8 + gr;
                b[nt] = *(const uint2*)(Bs + n * XW_CHUNK + kb);
            }
            #pragma unroll
            for (int mt = 0; mt < 4; mt++)
                #pragma unroll
                for (int nt = 0; nt < 4; nt++)
                    mma_tf32(acc[mt][nt][0], acc[mt][nt][1], acc[mt][nt][2], acc[mt][nt][3],
                             a[mt][0].x, a[mt][1].x, a[mt][0].y, a[mt][1].y,
                             b[nt].x, b[nt].y);
        }
        __syncthreads();
    }

    #pragma unroll
    for (int mt = 0; mt < 4; mt++) {
        int r1 = m0 + wm + mt * 16 + gr;
        #pragma unroll
        for (int nt = 0; nt < 4; nt++) {
            int col = n0 + wn + nt * 8 + 2 * gc;
            float2 v0 = { acc[mt][nt][0], acc[mt][nt][1] };
            float2 v1 = { acc[mt][nt][2], acc[mt][nt][3] };
            *(float2*)(C + (size_t)r1 * 768 + col) = v0;
            *(float2*)(C + (size_t)(r1 + 8) * 768 + col) = v1;
        }
    }
}

// ---------------- persistent GRU + helpers (Wfull chain, then incremental Q2) ----
// blocks 0..135: GRU recurrence (node blocks publish hall[t] via g_barq).
// blocks 136..147: Wfull chain; blocks 136..143 then compute Q2 per-timestep
// in the GRU's shadow (bit-identical to the old sgemm_q2: k-ascending fp32 FMA).
__global__ __launch_bounds__(256, 1) void gru_persist(
    const float* __restrict__ gi,
    const float* __restrict__ Whh_node, const float* __restrict__ Whh_ngh,
    const float* __restrict__ bih_node, const float* __restrict__ bhh_node,
    const float* __restrict__ bih_ngh,  const float* __restrict__ bhh_ngh,
    const float* __restrict__ wvc, const float* __restrict__ h0f,
    uint32_t* __restrict__ hx0, uint32_t* __restrict__ hx1,
    float* __restrict__ outp,
    float* __restrict__ hall, float* __restrict__ vp_part,
    const float* __restrict__ Wq, const float* __restrict__ Wbil,
    const float* __restrict__ Wk,
    float* __restrict__ tmp, float* __restrict__ WfullT,
    float* __restrict__ Q2)
{
    extern __shared__ uint32_t sh[];
    int tid = threadIdx.x;
    int bx = blockIdx.x;

    if (bx >= NBLK) {
        // ---- helper blocks ----
        int hb = bx - NBLK;                 // 0..11
        {
            float* As = (float*)sh;         // 16 x 68
            float* Bs = (float*)sh + 16 * 68;
            for (int ti = hb; ti < 16; ti += NHELP)
                tmp_tile(Wq, Wbil, tmp, As, Bs, (ti & 3) * 64, (ti >> 2) * 64);
            __syncthreads();
            if (tid == 0) { bar_arrive(&g_barh); bar_wait(&g_barh, NHELP); }
            __syncthreads();
            for (int ti = hb; ti < 16; ti += NHELP)
                wfull_tile(tmp, Wk, WfullT, As, Bs, (ti & 3) * 64, (ti >> 2) * 64);
            __syncthreads();
            if (tid == 0) bar_arrive(&g_barh);
        }
        if (hb >= 8) return;

        // ---- incremental Q2: helper hb owns cols [hb*32, hb*32+32) ----
        if (tid == 0) bar_wait(&g_barh, 2 * NHELP);   // all WfullT tiles done
        __syncthreads();
        float* Wq2 = (float*)sh;                      // [k*32 + c], 256x32
        float* Hq  = (float*)sh + 8192;               // [row*260 + k], 64x260 (padded)
        int c0 = hb * 32;
        for (int i = tid; i < 8192; i += 256) {
            int k = i >> 5, c = i & 31;
            Wq2[i] = WfullT[(size_t)(c0 + c) * 256 + k];
        }
        __syncthreads();
        int r = tid >> 2, cg = tid & 3;
        for (int t = 0; t < T_; t++) {
            if (tid == 0) bar_wait(&g_barq, 8u * (t + 1));
            __syncthreads();
            for (int i = tid; i < 4096; i += 256) {
                int row = i >> 6, kq = (i & 63) * 4;
                *(float4*)&Hq[row * 260 + kq] =
                    *(const float4*)&hall[((size_t)row * 1088 + t) * 256 + kq];
            }
            __syncthreads();
            float acc[8] = {};
            for (int k = 0; k < 256; k++) {
                float a = Hq[r * 260 + k];
                float4 b0 = *(const float4*)&Wq2[k * 32 + cg * 8];
                float4 b1 = *(const float4*)&Wq2[k * 32 + cg * 8 + 4];
                acc[0] += a * b0.x; acc[1] += a * b0.y;
                acc[2] += a * b0.z; acc[3] += a * b0.w;
                acc[4] += a * b1.x; acc[5] += a * b1.y;
                acc[6] += a * b1.z; acc[7] += a * b1.w;
            }
            float* dst = Q2 + ((size_t)r * 64 + t) * 256 + c0 + cg * 8;
            *(float4*)dst       = make_float4(acc[0], acc[1], acc[2], acc[3]);
            *(float4*)(dst + 4) = make_float4(acc[4], acc[5], acc[6], acc[7]);
            __syncthreads();
        }
        return;
    }

    uint32_t* Ws = sh;                              // 96 x 264 fragment-pair
    uint32_t* Hs = sh + GRU_WS_WORDS;               // 64 x 264 fragment-pair
    float* GH = (float*)(sh + GRU_WS_WORDS + GRU_HS_WORDS);   // 64 x 100
    uint32_t hs_base = (uint32_t)__cvta_generic_to_shared(Hs);

    int warp = tid >> 5, lane = tid & 31;
    int gr = lane >> 2, gc = lane & 3;
    int jt = bx & 7, mt = bx >> 3;
    int j0 = jt * 32, m0 = mt * 64;
    bool is_node = (mt == 0);
    const float* Whh = is_node ? Whh_node : Whh_ngh;
    int wm = (warp >> 2) * 32;         // 0 or 32
    int wn = (warp & 3) * 24;          // 0,24,48,72
    unsigned* mybar = &g_barm[mt * 32];

    // ---- load + repack weight slice once ----
    for (int c = tid; c < 3072; c += 256) {
        int n = c >> 5, kk = c & 31;
        int g = n >> 5, uu = n & 31;
        const float4* src = (const float4*)(Whh + (size_t)(g * 256 + j0 + uu) * 256 + kk * 8);
        float4 v0 = src[0], v1 = src[1];
        uint32_t* d = Ws + n * WSTR + kk * 8;
        *(uint4*)(d)     = make_uint4(f2tf32(v0.x), f2tf32(v1.x), f2tf32(v0.y), f2tf32(v1.y));
        *(uint4*)(d + 4) = make_uint4(f2tf32(v0.z), f2tf32(v1.z), f2tf32(v0.w), f2tf32(v1.w));
    }

    const float* bih = is_node ? bih_node : bih_ngh;
    const float* bhh = is_node ? bhh_node : bhh_ngh;
    int j = j0 + lane;
    float bir = bih[j], biz = bih[256 + j], bin = bih[512 + j];
    float bhr = bhh[j], bhz = bhh[256 + j], bhn = bhh[512 + j];
    float wv = wvc[j];

    size_t pre_gi[8], pre_hall[8], pre_vp[8], pre_h[8], pre_hx[8];
    float hreg[8];
    int jp = (j & ~7) + perm8(j & 7);
    #pragma unroll
    for (int rr = 0; rr < 8; rr++) {
        int R = m0 + warp * 8 + rr;
        pre_gi[rr] = (size_t)R * 49152 + j;
        int b, m;
        if (R < B_) { b = R; m = 0; }
        else { int q = R - B_; b = q >> 4; m = (q & 15) + 1; }
        size_t hallrow0 = ((size_t)b * M_ + m) * 64;
        pre_hall[rr] = hallrow0 * 256 + j;
        pre_vp[rr]  = (size_t)jt * FLATR + hallrow0;
        pre_h[rr]   = (size_t)R * 256 + j;
        pre_hx[rr]  = (size_t)R * 256 + jp;
        hreg[rr] = h0f[pre_h[rr]];
    }
    __syncthreads();

    float p_ir[8], p_iz[8], p_in[8];
    #pragma unroll
    for (int rr = 0; rr < 8; rr++) {
        p_ir[rr] = __ldg(gi + pre_gi[rr]);
        p_iz[rr] = __ldg(gi + pre_gi[rr] + 256);
        p_in[rr] = __ldg(gi + pre_gi[rr] + 512);
    }

    for (int t = 0; t < T_; t++) {
        const uint32_t* hxcur = (t & 1) ? hx1 : hx0;
        uint32_t* hxnext = (t & 1) ? hx0 : hx1;

        // ---- stage h tile in two k-half cp.async groups ----
        for (int idx = tid; idx < 2048; idx += 256) {
            int r = idx >> 5, seg = idx & 31;
            cp_async16_cg(hs_base + (uint32_t)(r * WSTR + seg * 4) * 4u,
                          hxcur + (size_t)(m0 + r) * 256 + seg * 4);
        }
        cp_commit();
        for (int idx = tid; idx < 2048; idx += 256) {
            int r = idx >> 5, seg = (idx & 31) + 32;
            cp_async16_cg(hs_base + (uint32_t)(r * WSTR + seg * 4) * 4u,
                          hxcur + (size_t)(m0 + r) * 256 + seg * 4);
        }
        cp_commit();

        float acc[2][3][4] = {};
        cp_wait<1>();
        __syncthreads();

        // ---- gh first k-half (kk 0..15) overlapping second-half loads ----
        #pragma unroll
        for (int kk = 0; kk < 16; kk++) {
            int kb = kk * 8 + gc * 2;
            uint2 av[2][2];
            #pragma unroll
            for (int mm = 0; mm < 2; mm++) {
                int r = wm + mm * 16 + gr;
                av[mm][0] = *(const uint2*)(Hs + r * WSTR + kb);
                av[mm][1] = *(const uint2*)(Hs + (r + 8) * WSTR + kb);
            }
            uint2 bv[3];
            #pragma unroll
            for (int nt = 0; nt < 3; nt++) {
                int n = wn + nt * 8 + gr;
                bv[nt] = *(const uint2*)(Ws + n * WSTR + kb);
            }
            #pragma unroll
            for (int mm = 0; mm < 2; mm++)
                #pragma unroll
                for (int nt = 0; nt < 3; nt++)
                    mma_tf32(acc[mm][nt][0], acc[mm][nt][1], acc[mm][nt][2], acc[mm][nt][3],
                             av[mm][0].x, av[mm][1].x, av[mm][0].y, av[mm][1].y,
                             bv[nt].x, bv[nt].y);
        }

        cp_wait<0>();
        __syncthreads();

        // ---- gh second k-half (kk 16..31) ----
        #pragma unroll
        for (int kk = 16; kk < 32; kk++) {
            int kb = kk * 8 + gc * 2;
            uint2 av[2][2];
            #pragma unroll
            for (int mm = 0; mm < 2; mm++) {
                int r = wm + mm * 16 + gr;
                av[mm][0] = *(const uint2*)(Hs + r * WSTR + kb);
                av[mm][1] = *(const uint2*)(Hs + (r + 8) * WSTR + kb);
            }
            uint2 bv[3];
            #pragma unroll
            for (int nt = 0; nt < 3; nt++) {
                int n = wn + nt * 8 + gr;
                bv[nt] = *(const uint2*)(Ws + n * WSTR + kb);
            }
            #pragma unroll
            for (int mm = 0; mm < 2; mm++)
                #pragma unroll
                for (int nt = 0; nt < 3; nt++)
                    mma_tf32(acc[mm][nt][0], acc[mm][nt][1], acc[mm][nt][2], acc[mm][nt][3],
                             av[mm][0].x, av[mm][1].x, av[mm][0].y, av[mm][1].y,
                             bv[nt].x, bv[nt].y);
        }

        // GH is a separate buffer: store without an extra barrier
        #pragma unroll
        for (int mm = 0; mm < 2; mm++) {
            int r1 = wm + mm * 16 + gr;
            #pragma unroll
            for (int nt = 0; nt < 3; nt++) {
                int col = wn + nt * 8 + 2 * gc;
                GH[r1 * 100 + col]           = acc[mm][nt][0];
                GH[r1 * 100 + col + 1]       = acc[mm][nt][1];
                GH[(r1 + 8) * 100 + col]     = acc[mm][nt][2];
                GH[(r1 + 8) * 100 + col + 1] = acc[mm][nt][3];
            }
        }
        __syncthreads();

        // ---- gates (critical path): hnew -> permuted hx store ----
        #pragma unroll
        for (int rr = 0; rr < 8; rr++) {
            int row = warp * 8 + rr;
            float gir = p_ir[rr] + bir;
            float giz = p_iz[rr] + biz;
            float gin = p_in[rr] + bin;
            float ghr = GH[row * 100 + lane]      + bhr;
            float ghz = GH[row * 100 + 32 + lane] + bhz;
            float ghn = GH[row * 100 + 64 + lane] + bhn;
            float r = fsigmoid(gir + ghr);
            float z = fsigmoid(giz + ghz);
            float n = ftanh(gin + r * ghn);
            float hnew = (1.f - z) * n + z * hreg[rr];
            hreg[rr] = hnew;
            hxnext[pre_hx[rr]] = f2tf32(hnew);
        }
        __syncthreads();
        if (tid == 0) bar_arrive(mybar);

        // ---- barrier shadow: hall/vp writes + gi prefetch ----
        #pragma unroll
        for (int rr = 0; rr < 8; rr++) {
            hall[pre_hall[rr] + (size_t)t * 256] = hreg[rr];
            float pv = hreg[rr] * wv;
            #pragma unroll
            for (int o = 16; o; o >>= 1) pv += __shfl_xor_sync(0xffffffffu, pv, o);
            if (lane == 0) vp_part[pre_vp[rr] + t] = pv;
        }
        if (is_node) {           // publish hall[t] for the Q2 helpers
            __syncthreads();
            if (tid == 0) bar_arrive(&g_barq);
        }
        if (t + 1 < T_) {
            #pragma unroll
            for (int rr = 0; rr < 8; rr++) {
                p_ir[rr] = __ldg(gi + pre_gi[rr] + (size_t)(t + 1) * 768);
                p_iz[rr] = __ldg(gi + pre_gi[rr] + (size_t)(t + 1) * 768 + 256);
                p_in[rr] = __ldg(gi + pre_gi[rr] + (size_t)(t + 1) * 768 + 512);
            }
        }
        if (tid == 0) bar_wait(mybar, 8u * (t + 1));
        __syncthreads();
    }

    // final hidden state written directly into the output tensor
    #pragma unroll
    for (int rr = 0; rr < 8; rr++) {
        int R = m0 + warp * 8 + rr;
        if (is_node) outp[OFF_NHT + R * 256 + j] = hreg[rr];
        else         outp[OFF_GHT + (R - B_) * 256 + j] = hreg[rr];
    }
}

// ---------------- attention, 2 slots per block ----------------
__global__ __launch_bounds__(256) void attn2_kernel(
    const float* __restrict__ Q2, const float* __restrict__ hall,
    const float* __restrict__ vp_part, const float* __restrict__ bbil,
    float* __restrict__ A_out, float* __restrict__ po)
{
    __shared__ float Qs[16][64];
    __shared__ float Ks[16][128];
    __shared__ float Ssm[64 * 130];
    __shared__ float vps[128];
    __shared__ float bb[64];

    int b = blockIdx.x;
    int g = blockIdx.y;
    int m0s = 2 * g;
    int nslot = (m0s + 1 < M_) ? 2 : 1;
    int tid = threadIdx.x;
    const float* qsrc = Q2 + (size_t)b * T_ * H_;

    if (tid < 64) bb[tid] = bbil[tid];
    if (tid < 128) {
        int slot = tid >> 6;
        float s = 0.f;
        if (slot < nslot) {
            int bm = b * M_ + m0s + slot;
            #pragma unroll
            for (int jt = 0; jt < 8; jt++)
                s += vp_part[(size_t)jt * FLATR + bm * 64 + (tid & 63)];
        }
        vps[tid] = s;
    }

    int tx = tid & 15, ty = tid >> 4;
    float acc[4][8] = {};
    for (int k0 = 0; k0 < H_; k0 += 16) {
        #pragma unroll
        for (int i = 0; i < 4; i++) {
            int idx = tid + i * 256;
            int r = idx >> 4, c = idx & 15;
            Qs[c][r] = qsrc[r * H_ + k0 + c];
        }
        #pragma unroll
        for (int i = 0; i < 8; i++) {
            int idx = tid + i * 256;
            int r = idx >> 4, c = idx & 15;
            int slot = r >> 6, rowin = r & 63;
            int m = m0s + slot; if (m > M_ - 1) m = M_ - 1;
            Ks[c][r] = hall[(((size_t)b * M_ + m) * 64 + rowin) * 256 + k0 + c];
        }
        __syncthreads();
        #pragma unroll
        for (int k = 0; k < 16; k++) {
            float q[4], kv[8];
            #pragma unroll
            for (int i = 0; i < 4; i++) q[i] = Qs[k][ty + 16 * i];
            #pragma unroll
            for (int jj = 0; jj < 8; jj++) kv[jj] = Ks[k][tx + 16 * jj];
            #pragma unroll
            for (int i = 0; i < 4; i++)
                #pragma unroll
                for (int jj = 0; jj < 8; jj++) acc[i][jj] += q[i] * kv[jj];
        }
        __syncthreads();
    }
    #pragma unroll
    for (int i = 0; i < 4; i++)
        #pragma unroll
        for (int jj = 0; jj < 8; jj++)
            Ssm[(ty + 16 * i) * 130 + tx + 16 * jj] = acc[i][jj];
    __syncthreads();

    int warp = tid >> 5, lane = tid & 31;
    for (int rr = 0; rr < 16; rr++) {
        int r = warp * 16 + rr;
        int slot = r >> 6, t = r & 63;
        if (slot >= nslot) break;
        int base = t * 130 + slot * 64;
        int s2 = lane + 32;
        bool v1ok = (lane <= t), v2ok = (s2 <= t);
        float v1 = v1ok ? Ssm[base + lane] + bb[lane] : -3.0e38f;
        float v2 = v2ok ? Ssm[base + s2]   + bb[s2]   : -3.0e38f;
        float mx = fmaxf(v1, v2);
        #pragma unroll
        for (int o = 16; o; o >>= 1) mx = fmaxf(mx, __shfl_xor_sync(0xffffffffu, mx, o));
        float p1 = v1ok ? __expf(v1 - mx) : 0.f;
        float p2 = v2ok ? __expf(v2 - mx) : 0.f;
        float sum = p1 + p2;
        #pragma unroll
        for (int o = 16; o; o >>= 1) sum += __shfl_xor_sync(0xffffffffu, sum, o);
        float inv = __fdividef(1.f, sum);
        float a1 = p1 * inv, a2 = p2 * inv;
        int bm = b * M_ + m0s + slot;
        size_t abase = ((size_t)bm * 64 + t) * 64;
        A_out[abase + lane]      = a1;
        A_out[abase + lane + 32] = a2;
        float pv = a1 * vps[slot * 64 + lane] + a2 * vps[slot * 64 + s2];
        #pragma unroll
        for (int o = 16; o; o >>= 1) pv += __shfl_xor_sync(0xffffffffu, pv, o);
        if (lane == 0) po[bm * 64 + t] = pv;
    }
}

// ---------------- finalize: out reduce over slots (hT written by gru) ------------
__global__ void finalize(const float* __restrict__ po, const float* __restrict__ bprj,
                         float* __restrict__ out) {
    int idx = blockIdx.x * 256 + threadIdx.x;
    int b = idx >> 6, t = idx & 63;
    float s = 17.f * bprj[0];
    #pragma unroll
    for (int m = 0; m < M_; m++) s += po[(b * M_ + m) * 64 + t];
    out[idx] = s;
}

// ---------------- launch ----------------
extern "C" void kernel_launch(void* const* d_in, const int* in_sizes, int n_in,
                              void* d_out, int out_size) {
    const float* node_input   = (const float*)d_in[0];
    const float* node_hidden  = (const float*)d_in[1];
    const float* ngh_input    = (const float*)d_in[2];
    const float* ngh_hidden   = (const float*)d_in[3];
    // d_in[4] = s_len (unused by reference)
    const float* Wih_node = (const float*)d_in[5];
    const float* Whh_node = (const float*)d_in[6];
    const float* bih_node = (const float*)d_in[7];
    const float* bhh_node = (const float*)d_in[8];
    const float* Wih_ngh  = (const float*)d_in[9];
    const float* Whh_ngh  = (const float*)d_in[10];
    const float* bih_ngh  = (const float*)d_in[11];
    const float* bhh_ngh  = (const float*)d_in[12];
    const float* Wq   = (const float*)d_in[13];
    const float* Wk   = (const float*)d_in[14];
    const float* Wv   = (const float*)d_in[15];
    const float* Wbil = (const float*)d_in[16];
    const float* bbil = (const float*)d_in[17];
    const float* Wprj = (const float*)d_in[18];
    const float* bprj = (const float*)d_in[19];
    float* out = (float*)d_out;

    float *gi, *h0, *hall, *Q2, *tmp, *WfullT, *wvc, *vpd, *pod;
    uint32_t *hx0, *hx1, *xt, *wt;
    cudaGetSymbolAddress((void**)&gi, g_gi);
    cudaGetSymbolAddress((void**)&xt, g_xt);
    cudaGetSymbolAddress((void**)&wt, g_wt);
    cudaGetSymbolAddress((void**)&h0, g_h0);
    cudaGetSymbolAddress((void**)&hx0, g_hx0);
    cudaGetSymbolAddress((void**)&hx1, g_hx1);
    cudaGetSymbolAddress((void**)&hall, g_hall);
    cudaGetSymbolAddress((void**)&Q2, g_Q2);
    cudaGetSymbolAddress((void**)&tmp, g_tmp);
    cudaGetSymbolAddress((void**)&WfullT, g_WfullT);
    cudaGetSymbolAddress((void**)&wvc, g_wvc);
    cudaGetSymbolAddress((void**)&vpd, g_vp);
    cudaGetSymbolAddress((void**)&pod, g_po);

    static int smem_set = 0;
    if (!smem_set) {
        cudaFuncSetAttribute(gru_persist, cudaFuncAttributeMaxDynamicSharedMemorySize,
                             GRU_SMEM_WORDS * 4);
        cudaFuncSetAttribute(gemm_xw, cudaFuncAttributeMaxDynamicSharedMemorySize,
                             XW_SMEM_WORDS * 4);
        smem_set = 1;
    }

    // 0: fused conv + init_h + wvc + barrier resets
    conv_all<<<CONVB + RALL + 1, 256>>>(node_input, ngh_input, Wih_node, Wih_ngh,
                                        node_hidden, ngh_hidden, Wprj, Wv,
                                        xt, wt, h0, hx0, wvc);

    // 1-2: input-side GEMMs
    gemm_xw<<<dim3(6, 32), 256, XW_SMEM_WORDS * 4>>>(xt, wt, gi);
    gemm_xw<<<dim3(6, 512), 256, XW_SMEM_WORDS * 4>>>(xt + (size_t)4096 * 128,
                                                      wt + 768 * 128,
                                                      gi + (size_t)4096 * 768);

    // 3: persistent recurrence + helpers (Wfull chain, then incremental Q2)
    gru_persist<<<GRID_GRU, 256, GRU_SMEM_WORDS * 4>>>(gi, Whh_node, Whh_ngh,
                                                       bih_node, bhh_node, bih_ngh, bhh_ngh,
                                                       wvc, h0, hx0, hx1, out, hall, vpd,
                                                       Wq, Wbil, Wk, tmp, WfullT, Q2);

    // 4-5: attention + finalize
    attn2_kernel<<<dim3(B_, 9), 256>>>(Q2, hall, vpd, bbil, out + OFF_A, pod);
    finalize<<<16, 256>>>(pod, bprj, out);
}

// round 17
// speedup vs baseline: 1.7332x; 1.7332x over previous
#include <cuda_runtime.h>
#include <cuda_bf16.h>
#include <math.h>
#include <stdint.h>

// Problem dims
#define B_  64
#define N_  16
#define T_  64
#define D_  128
#define H_  256
#define M_  17          // N+1 slots
#define RALL 1088       // B + B*N batch rows
#define FLATR 69632     // RALL*T  (also B*M_*T_)
#define NBLK 136        // persistent GRU blocks (8 j-tiles x 17 m-tiles)
#define NHELP 12        // helper blocks for the Wfull chain
#define GRID_GRU (NBLK + NHELP)

// Output offsets (concat of: out(4096), node_hT(16384), ngh_hT(262144), A(4456448))
#define OFF_OUT 0
#define OFF_NHT 4096
#define OFF_GHT 20480
#define OFF_A   282624

// gru smem layout (words)
#define WSTR 264                          // fragment-pair stride per row
#define GRU_WS_WORDS (96 * WSTR)
#define GRU_HS_WORDS (64 * WSTR)
#define GRU_GH_WORDS (64 * 100)
#define GRU_SMEM_WORDS (GRU_WS_WORDS + GRU_HS_WORDS + GRU_GH_WORDS)

// gemm_xw pipeline smem (words): chunk stride 40 (mod32=8 -> conflict-free LDS.64)
#define XW_CHUNK 40
#define XW_MAT   (128 * XW_CHUNK)
#define XW_SMEM_WORDS (4 * XW_MAT)        // As0, As1, Bs0, Bs1

// conv grid split
#define CONV_X_ITEMS (FLATR * 16)        // 8 words per item
#define CONV_W_ITEMS (768 * 16)
#define CONVB ((CONV_X_ITEMS + 2 * CONV_W_ITEMS) / 256)   // 4448

// ---------------- device scratch (no runtime allocation allowed) ----------------
__device__ float    g_gi[(size_t)FLATR * 768];   // precomputed x@Wih.T, [(r*T+t)*768+j]
__device__ uint32_t g_xt[(size_t)FLATR * 128];   // tf32 pre-permuted X (node rows first)
__device__ uint32_t g_wt[2 * 768 * 128];         // tf32 pre-permuted Wih (node, ngh)
__device__ float    g_h0[RALL * H_];             // fp32 initial h
__device__ uint32_t g_hx0[RALL * H_];            // tf32 exchange ping (perm8 order)
__device__ uint32_t g_hx1[RALL * H_];            // tf32 exchange pong (perm8 order)
__device__ float    g_hall[(size_t)FLATR * H_];  // kv layout [((b*17+m)*64+t)*256+h]
__device__ float    g_Q2[(size_t)B_ * T_ * H_];
__device__ float    g_tmp[H_ * H_];              // Wq^T @ Wbil
__device__ float    g_WfullT[H_ * H_];           // (Wq^T Wbil Wk) transposed
__device__ float    g_wvc[H_];                   // Wprj @ Wv
__device__ float    g_vp[8 * FLATR];             // per-jt partial hall.wvc
__device__ float    g_po[B_ * M_ * T_];          // per-slot partial output
__device__ unsigned g_barm[M_ * 32];             // per-m-tile barrier counters, 128B apart
__device__ unsigned g_barh;                      // helper-phase barrier counter

// ---------------- helpers ----------------
__device__ __forceinline__ uint32_t f2tf32(float f) {
    uint32_t o;
    asm("cvt.rna.tf32.f32 %0, %1;" : "=r"(o) : "f"(f));
    return o;
}

__device__ __forceinline__ void mma_tf32(float& d0, float& d1, float& d2, float& d3,
                                         uint32_t a0, uint32_t a1, uint32_t a2, uint32_t a3,
                                         uint32_t b0, uint32_t b1) {
    asm volatile(
        "mma.sync.aligned.m16n8k8.row.col.f32.tf32.tf32.f32 "
        "{%0,%1,%2,%3}, {%4,%5,%6,%7}, {%8,%9}, {%0,%1,%2,%3};\n"
        : "+f"(d0), "+f"(d1), "+f"(d2), "+f"(d3)
        : "r"(a0), "r"(a1), "r"(a2), "r"(a3), "r"(b0), "r"(b1));
}

__device__ __forceinline__ float fsigmoid(float x) {
    return __fdividef(1.f, 1.f + __expf(-x));
}
__device__ __forceinline__ float ftanh(float x) {
    return 1.f - __fdividef(2.f, 1.f + __expf(2.f * x));
}

__device__ __forceinline__ void cp_async16(uint32_t dst, const void* src) {
    asm volatile("cp.async.ca.shared.global [%0], [%1], 16;" :: "r"(dst), "l"(src));
}
__device__ __forceinline__ void cp_async16_cg(uint32_t dst, const void* src) {
    asm volatile("cp.async.cg.shared.global [%0], [%1], 16;" :: "r"(dst), "l"(src));
}
__device__ __forceinline__ void cp_commit() {
    asm volatile("cp.async.commit_group;" ::: "memory");
}
template <int N>
__device__ __forceinline__ void cp_wait() {
    asm volatile("cp.async.wait_group %0;" :: "n"(N) : "memory");
}

__device__ __forceinline__ void bar_arrive(unsigned* p) {
    asm volatile("red.release.gpu.add.u32 [%0], %1;" :: "l"(p), "r"(1u) : "memory");
}
__device__ __forceinline__ void bar_wait(unsigned* p, unsigned target) {
    unsigned v;
    do {
        asm volatile("ld.acquire.gpu.u32 %0, [%1];" : "=r"(v) : "l"(p) : "memory");
    } while (v < target);
}

// fragment-pair permutation within an 8-word k-group
__device__ __forceinline__ int perm8(int k) {
    return ((k & 3) << 1) | ((k >> 2) & 1);
}

// permute 8 consecutive k-words into fragment-pair order + tf32 convert
__device__ __forceinline__ void conv_pack8(const float* __restrict__ src,
                                           uint32_t* __restrict__ dst) {
    float4 v0 = *(const float4*)(src);
    float4 v1 = *(const float4*)(src + 4);
    *(uint4*)(dst)     = make_uint4(f2tf32(v0.x), f2tf32(v1.x), f2tf32(v0.y), f2tf32(v1.y));
    *(uint4*)(dst + 4) = make_uint4(f2tf32(v0.z), f2tf32(v1.z), f2tf32(v0.w), f2tf32(v1.w));
}

// ---------------- fused pass: conv(X,Wih) + init_h + wvc + barrier resets --------
__global__ void conv_all(const float* __restrict__ node_input,
                         const float* __restrict__ ngh_input,
                         const float* __restrict__ Wih_node,
                         const float* __restrict__ Wih_ngh,
                         const float* __restrict__ node_hidden,
                         const float* __restrict__ ngh_hidden,
                         const float* __restrict__ Wprj, const float* __restrict__ Wv,
                         uint32_t* __restrict__ xt, uint32_t* __restrict__ wt,
                         float* __restrict__ h, uint32_t* __restrict__ hx,
                         float* __restrict__ wvc) {
    int bx = blockIdx.x;
    if (bx < CONVB) {
        int idx = bx * 256 + threadIdx.x;
        if (idx < CONV_X_ITEMS) {
            size_t off = (size_t)idx * 8;
            const float* src = (off < (size_t)4096 * 128)
                             ? node_input + off
                             : ngh_input + (off - (size_t)4096 * 128);
            conv_pack8(src, xt + off);
        } else {
            int w = idx - CONV_X_ITEMS;
            size_t off = (size_t)(w % CONV_W_ITEMS) * 8;
            const float* src = (w < CONV_W_ITEMS) ? Wih_node + off : Wih_ngh + off;
            conv_pack8(src, wt + (w < CONV_W_ITEMS ? 0 : 768 * 128) + off);
        }
    } else if (bx < CONVB + RALL) {
        int row = bx - CONVB, u = threadIdx.x;
        float v = (row < B_) ? node_hidden[row * H_ + u]
                             : ngh_hidden[(row - B_) * H_ + u];
        h[row * H_ + u] = v;
        hx[row * H_ + (u & ~7) + perm8(u & 7)] = f2tf32(v);
    } else {
        int hp = threadIdx.x;
        float acc[8] = {};
        for (int h0 = 0; h0 < H_; h0 += 8) {
            #pragma unroll
            for (int u = 0; u < 8; u++)
                acc[u] += Wprj[h0 + u] * Wv[(size_t)(h0 + u) * H_ + hp];
        }
        wvc[hp] = ((acc[0] + acc[1]) + (acc[2] + acc[3])) +
                  ((acc[4] + acc[5]) + (acc[6] + acc[7]));
        if (hp < M_) g_barm[hp * 32] = 0;   // reset every launch/replay
        if (hp == 32) g_barh = 0;
    }
}

// ---------------- helper tile bodies (identical math to prior prep kernels) ------
__device__ void tmp_tile(const float* __restrict__ Wq, const float* __restrict__ Wbil,
                         float* __restrict__ tmp, float* As, float* Bs,
                         int k0, int c0) {
    int tid = threadIdx.x, tx = tid & 15, ty = tid >> 4;
    float acc[4][4] = {};
    for (int a0 = 0; a0 < H_; a0 += 16) {
        #pragma unroll
        for (int i = tid; i < 1024; i += 256) {
            int a = i >> 6, q = i & 63;
            As[a * 68 + q] = Wq[(size_t)(a0 + a) * H_ + k0 + q];
            Bs[a * 68 + q] = Wbil[(size_t)(a0 + a) * H_ + c0 + q];
        }
        __syncthreads();
        #pragma unroll
        for (int a = 0; a < 16; a++) {
            float4 av = *(const float4*)&As[a * 68 + ty * 4];
            float4 bv = *(const float4*)&Bs[a * 68 + tx * 4];
            float aa[4] = { av.x, av.y, av.z, av.w };
            float bb[4] = { bv.x, bv.y, bv.z, bv.w };
            #pragma unroll
            for (int i = 0; i < 4; i++)
                #pragma unroll
                for (int j = 0; j < 4; j++) acc[i][j] += aa[i] * bb[j];
        }
        __syncthreads();
    }
    #pragma unroll
    for (int i = 0; i < 4; i++)
        *(float4*)&tmp[(size_t)(k0 + ty * 4 + i) * H_ + c0 + tx * 4] =
            make_float4(acc[i][0], acc[i][1], acc[i][2], acc[i][3]);
}

__device__ void wfull_tile(const float* __restrict__ tmp, const float* __restrict__ Wk,
                           float* __restrict__ WfullT, float* As, float* Bs,
                           int k0, int hp0) {
    int tid = threadIdx.x, tx = tid & 15, ty = tid >> 4;
    float acc[4][4] = {};
    for (int c0 = 0; c0 < H_; c0 += 16) {
        #pragma unroll
        for (int i = tid; i < 1024; i += 256) {
            int r = i >> 4, c = i & 15;
            As[c * 68 + r] = tmp[(size_t)(k0 + r) * H_ + c0 + c];
        }
        #pragma unroll
        for (int i = tid; i < 1024; i += 256) {
            int c = i >> 6, q = i & 63;
            Bs[c * 68 + q] = Wk[(size_t)(c0 + c) * H_ + hp0 + q];
        }
        __syncthreads();
        #pragma unroll
        for (int c = 0; c < 16; c++) {
            float4 hv = *(const float4*)&Bs[c * 68 + ty * 4];
            float4 kv = *(const float4*)&As[c * 68 + tx * 4];
            float hh[4] = { hv.x, hv.y, hv.z, hv.w };
            float kk[4] = { kv.x, kv.y, kv.z, kv.w };
            #pragma unroll
            for (int i = 0; i < 4; i++)
                #pragma unroll
                for (int j = 0; j < 4; j++) acc[i][j] += hh[i] * kk[j];
        }
        __syncthreads();
    }
    #pragma unroll
    for (int i = 0; i < 4; i++)
        *(float4*)&WfullT[(size_t)(hp0 + ty * 4 + i) * H_ + k0 + tx * 4] =
            make_float4(acc[i][0], acc[i][1], acc[i][2], acc[i][3]);
}

// ---------------- pipelined tf32 GEMM on pre-converted operands ----------------
__global__ __launch_bounds__(256, 2) void gemm_xw(const uint32_t* __restrict__ X,
                                                  const uint32_t* __restrict__ W,
                                                  float* __restrict__ C) {
    extern __shared__ uint32_t xsh[];
    uint32_t sbase = (uint32_t)__cvta_generic_to_shared(xsh);
    int tid = threadIdx.x;
    int warp = tid >> 5, lane = tid & 31;
    int gr = lane >> 2, gc = lane & 3;
    int m0 = blockIdx.y * 128, n0 = blockIdx.x * 128;
    int wm = (warp >> 2) * 64, wn = (warp & 3) * 32;

    auto load_chunk = [&](int c, int p) {
        uint32_t abase = sbase + (uint32_t)(p * XW_MAT) * 4u;
        uint32_t bbase = sbase + (uint32_t)((2 + p) * XW_MAT) * 4u;
        #pragma unroll
        for (int s = 0; s < 4; s++) {
            int q = tid + s * 256;
            int row = q >> 3, seg = q & 7;
            uint32_t off = (uint32_t)(row * XW_CHUNK + seg * 4) * 4u;
            cp_async16(abase + off, X + (size_t)(m0 + row) * 128 + c * 32 + seg * 4);
            cp_async16(bbase + off, W + (size_t)(n0 + row) * 128 + c * 32 + seg * 4);
        }
        cp_commit();
    };

    float acc[4][4][4] = {};
    load_chunk(0, 0);

    for (int c = 0; c < 4; c++) {
        if (c < 3) { load_chunk(c + 1, (c + 1) & 1); cp_wait<1>(); }
        else       { cp_wait<0>(); }
        __syncthreads();

        const uint32_t* As = xsh + (c & 1) * XW_MAT;
        const uint32_t* Bs = xsh + (2 + (c & 1)) * XW_MAT;

        #pragma unroll
        for (int kk = 0; kk < 4; kk++) {
            int kb = kk * 8 + gc * 2;
            uint2 a[4][2];
            #pragma unroll
            for (int mt = 0; mt < 4; mt++) {
                int r = wm + mt * 16 + gr;
                a[mt][0] = *(const uint2*)(As + r * XW_CHUNK + kb);
                a[mt][1] = *(const uint2*)(As + (r + 8) * XW_CHUNK + kb);
            }
            uint2 b[4];
            #pragma unroll
            for (int nt = 0; nt < 4; nt++) {
                int n = wn + nt * 8 + gr;
                b[nt] = *(const uint2*)(Bs + n * XW_CHUNK + kb);
            }
            #pragma unroll
            for (int mt = 0; mt < 4; mt++)
                #pragma unroll
                for (int nt = 0; nt < 4; nt++)
                    mma_tf32(acc[mt][nt][0], acc[mt][nt][1], acc[mt][nt][2], acc[mt][nt][3],
                             a[mt][0].x, a[mt][1].x, a[mt][0].y, a[mt][1].y,
                             b[nt].x, b[nt].y);
        }
        __syncthreads();
    }

    #pragma unroll
    for (int mt = 0; mt < 4; mt++) {
        int r1 = m0 + wm + mt * 16 + gr;
        #pragma unroll
        for (int nt = 0; nt < 4; nt++) {
            int col = n0 + wn + nt * 8 + 2 * gc;
            float2 v0 = { acc[mt][nt][0], acc[mt][nt][1] };
            float2 v1 = { acc[mt][nt][2], acc[mt][nt][3] };
            *(float2*)(C + (size_t)r1 * 768 + col) = v0;
            *(float2*)(C + (size_t)(r1 + 8) * 768 + col) = v1;
        }
    }
}

// ---------------- persistent GRU + Wfull-chain helpers in one launch -------------
// blocks 0..135: GRU recurrence (writes hT directly to the output tensor).
// blocks 136..147: tmp -> WfullT chain in the GRU's shadow.
__global__ __launch_bounds__(256, 1) void gru_persist(
    const float* __restrict__ gi,
    const float* __restrict__ Whh_node, const float* __restrict__ Whh_ngh,
    const float* __restrict__ bih_node, const float* __restrict__ bhh_node,
    const float* __restrict__ bih_ngh,  const float* __restrict__ bhh_ngh,
    const float* __restrict__ wvc, const float* __restrict__ h0f,
    uint32_t* __restrict__ hx0, uint32_t* __restrict__ hx1,
    float* __restrict__ outp,
    float* __restrict__ hall, float* __restrict__ vp_part,
    const float* __restrict__ Wq, const float* __restrict__ Wbil,
    const float* __restrict__ Wk,
    float* __restrict__ tmp, float* __restrict__ WfullT)
{
    extern __shared__ uint32_t sh[];
    int tid = threadIdx.x;
    int bx = blockIdx.x;

    if (bx >= NBLK) {
        // ---- helper blocks: Wfull chain only ----
        int hb = bx - NBLK;                 // 0..11
        float* As = (float*)sh;             // 16 x 68
        float* Bs = (float*)sh + 16 * 68;
        for (int ti = hb; ti < 16; ti += NHELP)
            tmp_tile(Wq, Wbil, tmp, As, Bs, (ti & 3) * 64, (ti >> 2) * 64);
        __syncthreads();
        if (tid == 0) { bar_arrive(&g_barh); bar_wait(&g_barh, NHELP); }
        __syncthreads();
        for (int ti = hb; ti < 16; ti += NHELP)
            wfull_tile(tmp, Wk, WfullT, As, Bs, (ti & 3) * 64, (ti >> 2) * 64);
        return;
    }

    uint32_t* Ws = sh;                              // 96 x 264 fragment-pair
    uint32_t* Hs = sh + GRU_WS_WORDS;               // 64 x 264 fragment-pair
    float* GH = (float*)(sh + GRU_WS_WORDS + GRU_HS_WORDS);   // 64 x 100
    uint32_t hs_base = (uint32_t)__cvta_generic_to_shared(Hs);

    int warp = tid >> 5, lane = tid & 31;
    int gr = lane >> 2, gc = lane & 3;
    int jt = bx & 7, mt = bx >> 3;
    int j0 = jt * 32, m0 = mt * 64;
    bool is_node = (mt == 0);
    const float* Whh = is_node ? Whh_node : Whh_ngh;
    int wm = (warp >> 2) * 32;         // 0 or 32
    int wn = (warp & 3) * 24;          // 0,24,48,72
    unsigned* mybar = &g_barm[mt * 32];

    // ---- load + repack weight slice once ----
    for (int c = tid; c < 3072; c += 256) {
        int n = c >> 5, kk = c & 31;
        int g = n >> 5, uu = n & 31;
        const float4* src = (const float4*)(Whh + (size_t)(g * 256 + j0 + uu) * 256 + kk * 8);
        float4 v0 = src[0], v1 = src[1];
        uint32_t* d = Ws + n * WSTR + kk * 8;
        *(uint4*)(d)     = make_uint4(f2tf32(v0.x), f2tf32(v1.x), f2tf32(v0.y), f2tf32(v1.y));
        *(uint4*)(d + 4) = make_uint4(f2tf32(v0.z), f2tf32(v1.z), f2tf32(v0.w), f2tf32(v1.w));
    }

    const float* bih = is_node ? bih_node : bih_ngh;
    const float* bhh = is_node ? bhh_node : bhh_ngh;
    int j = j0 + lane;
    float bir = bih[j], biz = bih[256 + j], bin = bih[512 + j];
    float bhr = bhh[j], bhz = bhh[256 + j], bhn = bhh[512 + j];
    float wv = wvc[j];

    size_t pre_gi[8], pre_hall[8], pre_vp[8], pre_h[8], pre_hx[8];
    float hreg[8];
    int jp = (j & ~7) + perm8(j & 7);
    #pragma unroll
    for (int rr = 0; rr < 8; rr++) {
        int R = m0 + warp * 8 + rr;
        pre_gi[rr] = (size_t)R * 49152 + j;
        int b, m;
        if (R < B_) { b = R; m = 0; }
        else { int q = R - B_; b = q >> 4; m = (q & 15) + 1; }
        size_t hallrow0 = ((size_t)b * M_ + m) * 64;
        pre_hall[rr] = hallrow0 * 256 + j;
        pre_vp[rr]  = (size_t)jt * FLATR + hallrow0;
        pre_h[rr]   = (size_t)R * 256 + j;
        pre_hx[rr]  = (size_t)R * 256 + jp;
        hreg[rr] = h0f[pre_h[rr]];
    }
    __syncthreads();

    float p_ir[8], p_iz[8], p_in[8];
    #pragma unroll
    for (int rr = 0; rr < 8; rr++) {
        p_ir[rr] = __ldg(gi + pre_gi[rr]);
        p_iz[rr] = __ldg(gi + pre_gi[rr] + 256);
        p_in[rr] = __ldg(gi + pre_gi[rr] + 512);
    }

    for (int t = 0; t < T_; t++) {
        const uint32_t* hxcur = (t & 1) ? hx1 : hx0;
        uint32_t* hxnext = (t & 1) ? hx0 : hx1;

        // ---- stage h tile in two k-half cp.async groups ----
        for (int idx = tid; idx < 2048; idx += 256) {
            int r = idx >> 5, seg = idx & 31;
            cp_async16_cg(hs_base + (uint32_t)(r * WSTR + seg * 4) * 4u,
                          hxcur + (size_t)(m0 + r) * 256 + seg * 4);
        }
        cp_commit();
        for (int idx = tid; idx < 2048; idx += 256) {
            int r = idx >> 5, seg = (idx & 31) + 32;
            cp_async16_cg(hs_base + (uint32_t)(r * WSTR + seg * 4) * 4u,
                          hxcur + (size_t)(m0 + r) * 256 + seg * 4);
        }
        cp_commit();

        float acc[2][3][4] = {};
        cp_wait<1>();
        __syncthreads();

        // ---- gh first k-half (kk 0..15) overlapping second-half loads ----
        #pragma unroll
        for (int kk = 0; kk < 16; kk++) {
            int kb = kk * 8 + gc * 2;
            uint2 av[2][2];
            #pragma unroll
            for (int mm = 0; mm < 2; mm++) {
                int r = wm + mm * 16 + gr;
                av[mm][0] = *(const uint2*)(Hs + r * WSTR + kb);
                av[mm][1] = *(const uint2*)(Hs + (r + 8) * WSTR + kb);
            }
            uint2 bv[3];
            #pragma unroll
            for (int nt = 0; nt < 3; nt++) {
                int n = wn + nt * 8 + gr;
                bv[nt] = *(const uint2*)(Ws + n * WSTR + kb);
            }
            #pragma unroll
            for (int mm = 0; mm < 2; mm++)
                #pragma unroll
                for (int nt = 0; nt < 3; nt++)
                    mma_tf32(acc[mm][nt][0], acc[mm][nt][1], acc[mm][nt][2], acc[mm][nt][3],
                             av[mm][0].x, av[mm][1].x, av[mm][0].y, av[mm][1].y,
                             bv[nt].x, bv[nt].y);
        }

        cp_wait<0>();
        __syncthreads();

        // ---- gh second k-half (kk 16..31) ----
        #pragma unroll
        for (int kk = 16; kk < 32; kk++) {
            int kb = kk * 8 + gc * 2;
            uint2 av[2][2];
            #pragma unroll
            for (int mm = 0; mm < 2; mm++) {
                int r = wm + mm * 16 + gr;
                av[mm][0] = *(const uint2*)(Hs + r * WSTR + kb);
                av[mm][1] = *(const uint2*)(Hs + (r + 8) * WSTR + kb);
            }
            uint2 bv[3];
            #pragma unroll
            for (int nt = 0; nt < 3; nt++) {
                int n = wn + nt * 8 + gr;
                bv[nt] = *(const uint2*)(Ws + n * WSTR + kb);
            }
            #pragma unroll
            for (int mm = 0; mm < 2; mm++)
                #pragma unroll
                for (int nt = 0; nt < 3; nt++)
                    mma_tf32(acc[mm][nt][0], acc[mm][nt][1], acc[mm][nt][2], acc[mm][nt][3],
                             av[mm][0].x, av[mm][1].x, av[mm][0].y, av[mm][1].y,
                             bv[nt].x, bv[nt].y);
        }

        // GH is a separate buffer: store without an extra barrier
        #pragma unroll
        for (int mm = 0; mm < 2; mm++) {
            int r1 = wm + mm * 16 + gr;
            #pragma unroll
            for (int nt = 0; nt < 3; nt++) {
                int col = wn + nt * 8 + 2 * gc;
                GH[r1 * 100 + col]           = acc[mm][nt][0];
                GH[r1 * 100 + col + 1]       = acc[mm][nt][1];
                GH[(r1 + 8) * 100 + col]     = acc[mm][nt][2];
                GH[(r1 + 8) * 100 + col + 1] = acc[mm][nt][3];
            }
        }
        __syncthreads();

        // ---- gates (critical path): hnew -> permuted hx store ----
        #pragma unroll
        for (int rr = 0; rr < 8; rr++) {
            int row = warp * 8 + rr;
            float gir = p_ir[rr] + bir;
            float giz = p_iz[rr] + biz;
            float gin = p_in[rr] + bin;
            float ghr = GH[row * 100 + lane]      + bhr;
            float ghz = GH[row * 100 + 32 + lane] + bhz;
            float ghn = GH[row * 100 + 64 + lane] + bhn;
            float r = fsigmoid(gir + ghr);
            float z = fsigmoid(giz + ghz);
            float n = ftanh(gin + r * ghn);
            float hnew = (1.f - z) * n + z * hreg[rr];
            hreg[rr] = hnew;
            hxnext[pre_hx[rr]] = f2tf32(hnew);
        }
        __syncthreads();
        if (tid == 0) bar_arrive(mybar);

        // ---- barrier shadow: hall/vp writes + gi prefetch ----
        #pragma unroll
        for (int rr = 0; rr < 8; rr++) {
            hall[pre_hall[rr] + (size_t)t * 256] = hreg[rr];
            float pv = hreg[rr] * wv;
            #pragma unroll
            for (int o = 16; o; o >>= 1) pv += __shfl_xor_sync(0xffffffffu, pv, o);
            if (lane == 0) vp_part[pre_vp[rr] + t] = pv;
        }
        if (t + 1 < T_) {
            #pragma unroll
            for (int rr = 0; rr < 8; rr++) {
                p_ir[rr] = __ldg(gi + pre_gi[rr] + (size_t)(t + 1) * 768);
                p_iz[rr] = __ldg(gi + pre_gi[rr] + (size_t)(t + 1) * 768 + 256);
                p_in[rr] = __ldg(gi + pre_gi[rr] + (size_t)(t + 1) * 768 + 512);
            }
        }
        if (tid == 0) bar_wait(mybar, 8u * (t + 1));
        __syncthreads();
    }

    // final hidden state written directly into the output tensor
    #pragma unroll
    for (int rr = 0; rr < 8; rr++) {
        int R = m0 + warp * 8 + rr;
        if (is_node) outp[OFF_NHT + R * 256 + j] = hreg[rr];
        else         outp[OFF_GHT + (R - B_) * 256 + j] = hreg[rr];
    }
}

// ---------------- Q2 GEMM (fp32, reads node rows directly from hall) ----------------
__global__ __launch_bounds__(256) void sgemm_q2(const float* __restrict__ hall,
                                                const float* __restrict__ Bw,
                                                float* __restrict__ C) {
    __shared__ float As[8][128];
    __shared__ float Bs[8][128];
    int tid = threadIdx.x;
    int tx = tid & 15, ty = tid >> 4;
    int m0 = blockIdx.y * 128, n0 = blockIdx.x * 128;
    float acc[8][8] = {};
    for (int k0 = 0; k0 < 256; k0 += 8) {
        #pragma unroll
        for (int i = 0; i < 4; i++) {
            int idx = tid + i * 256;
            int r = idx >> 3, c = idx & 7;
            int row = m0 + r;
            size_t hrow = (size_t)(row >> 6) * 1088 + (row & 63);
            As[c][r] = hall[hrow * 256 + k0 + c];
            Bs[c][r] = Bw[(size_t)(n0 + r) * 256 + k0 + c];
        }
        __syncthreads();
        #pragma unroll
        for (int k = 0; k < 8; k++) {
            float a[8], bv[8];
            #pragma unroll
            for (int i = 0; i < 8; i++) a[i] = As[k][ty * 8 + i];
            #pragma unroll
            for (int jj = 0; jj < 8; jj++) bv[jj] = Bs[k][tx * 8 + jj];
            #pragma unroll
            for (int i = 0; i < 8; i++)
                #pragma unroll
                for (int jj = 0; jj < 8; jj++) acc[i][jj] += a[i] * bv[jj];
        }
        __syncthreads();
    }
    #pragma unroll
    for (int i = 0; i < 8; i++)
        #pragma unroll
        for (int jj = 0; jj < 8; jj++)
            C[(size_t)(m0 + ty * 8 + i) * 256 + n0 + tx * 8 + jj] = acc[i][jj];
}

// ---------------- attention, 2 slots per block ----------------
__global__ __launch_bounds__(256) void attn2_kernel(
    const float* __restrict__ Q2, const float* __restrict__ hall,
    const float* __restrict__ vp_part, const float* __restrict__ bbil,
    float* __restrict__ A_out, float* __restrict__ po)
{
    __shared__ float Qs[16][64];
    __shared__ float Ks[16][128];
    __shared__ float Ssm[64 * 130];
    __shared__ float vps[128];
    __shared__ float bb[64];

    int b = blockIdx.x;
    int g = blockIdx.y;
    int m0s = 2 * g;
    int nslot = (m0s + 1 < M_) ? 2 : 1;
    int tid = threadIdx.x;
    const float* qsrc = Q2 + (size_t)b * T_ * H_;

    if (tid < 64) bb[tid] = bbil[tid];
    if (tid < 128) {
        int slot = tid >> 6;
        float s = 0.f;
        if (slot < nslot) {
            int bm = b * M_ + m0s + slot;
            #pragma unroll
            for (int jt = 0; jt < 8; jt++)
                s += vp_part[(size_t)jt * FLATR + bm * 64 + (tid & 63)];
        }
        vps[tid] = s;
    }

    int tx = tid & 15, ty = tid >> 4;
    float acc[4][8] = {};
    for (int k0 = 0; k0 < H_; k0 += 16) {
        #pragma unroll
        for (int i = 0; i < 4; i++) {
            int idx = tid + i * 256;
            int r = idx >> 4, c = idx & 15;
            Qs[c][r] = qsrc[r * H_ + k0 + c];
        }
        #pragma unroll
        for (int i = 0; i < 8; i++) {
            int idx = tid + i * 256;
            int r = idx >> 4, c = idx & 15;
            int slot = r >> 6, rowin = r & 63;
            int m = m0s + slot; if (m > M_ - 1) m = M_ - 1;
            Ks[c][r] = hall[(((size_t)b * M_ + m) * 64 + rowin) * 256 + k0 + c];
        }
        __syncthreads();
        #pragma unroll
        for (int k = 0; k < 16; k++) {
            float q[4], kv[8];
            #pragma unroll
            for (int i = 0; i < 4; i++) q[i] = Qs[k][ty + 16 * i];
            #pragma unroll
            for (int jj = 0; jj < 8; jj++) kv[jj] = Ks[k][tx + 16 * jj];
            #pragma unroll
            for (int i = 0; i < 4; i++)
                #pragma unroll
                for (int jj = 0; jj < 8; jj++) acc[i][jj] += q[i] * kv[jj];
        }
        __syncthreads();
    }
    #pragma unroll
    for (int i = 0; i < 4; i++)
        #pragma unroll
        for (int jj = 0; jj < 8; jj++)
            Ssm[(ty + 16 * i) * 130 + tx + 16 * jj] = acc[i][jj];
    __syncthreads();

    int warp = tid >> 5, lane = tid & 31;
    for (int rr = 0; rr < 16; rr++) {
        int r = warp * 16 + rr;
        int slot = r >> 6, t = r & 63;
        if (slot >= nslot) break;
        int base = t * 130 + slot * 64;
        int s2 = lane + 32;
        bool v1ok = (lane <= t), v2ok = (s2 <= t);
        float v1 = v1ok ? Ssm[base + lane] + bb[lane] : -3.0e38f;
        float v2 = v2ok ? Ssm[base + s2]   + bb[s2]   : -3.0e38f;
        float mx = fmaxf(v1, v2);
        #pragma unroll
        for (int o = 16; o; o >>= 1) mx = fmaxf(mx, __shfl_xor_sync(0xffffffffu, mx, o));
        float p1 = v1ok ? __expf(v1 - mx) : 0.f;
        float p2 = v2ok ? __expf(v2 - mx) : 0.f;
        float sum = p1 + p2;
        #pragma unroll
        for (int o = 16; o; o >>= 1) sum += __shfl_xor_sync(0xffffffffu, sum, o);
        float inv = __fdividef(1.f, sum);
        float a1 = p1 * inv, a2 = p2 * inv;
        int bm = b * M_ + m0s + slot;
        size_t abase = ((size_t)bm * 64 + t) * 64;
        A_out[abase + lane]      = a1;
        A_out[abase + lane + 32] = a2;
        float pv = a1 * vps[slot * 64 + lane] + a2 * vps[slot * 64 + s2];
        #pragma unroll
        for (int o = 16; o; o >>= 1) pv += __shfl_xor_sync(0xffffffffu, pv, o);
        if (lane == 0) po[bm * 64 + t] = pv;
    }
}

// ---------------- finalize: out reduce over slots (hT written by gru) ------------
__global__ void finalize(const float* __restrict__ po, const float* __restrict__ bprj,
                         float* __restrict__ out) {
    int idx = blockIdx.x * 256 + threadIdx.x;
    int b = idx >> 6, t = idx & 63;
    float s = 17.f * bprj[0];
    #pragma unroll
    for (int m = 0; m < M_; m++) s += po[(b * M_ + m) * 64 + t];
    out[idx] = s;
}

// ---------------- launch ----------------
extern "C" void kernel_launch(void* const* d_in, const int* in_sizes, int n_in,
                              void* d_out, int out_size) {
    const float* node_input   = (const float*)d_in[0];
    const float* node_hidden  = (const float*)d_in[1];
    const float* ngh_input    = (const float*)d_in[2];
    const float* ngh_hidden   = (const float*)d_in[3];
    // d_in[4] = s_len (unused by reference)
    const float* Wih_node = (const float*)d_in[5];
    const float* Whh_node = (const float*)d_in[6];
    const float* bih_node = (const float*)d_in[7];
    const float* bhh_node = (const float*)d_in[8];
    const float* Wih_ngh  = (const float*)d_in[9];
    const float* Whh_ngh  = (const float*)d_in[10];
    const float* bih_ngh  = (const float*)d_in[11];
    const float* bhh_ngh  = (const float*)d_in[12];
    const float* Wq   = (const float*)d_in[13];
    const float* Wk   = (const float*)d_in[14];
    const float* Wv   = (const float*)d_in[15];
    const float* Wbil = (const float*)d_in[16];
    const float* bbil = (const float*)d_in[17];
    const float* Wprj = (const float*)d_in[18];
    const float* bprj = (const float*)d_in[19];
    float* out = (float*)d_out;

    float *gi, *h0, *hall, *Q2, *tmp, *WfullT, *wvc, *vpd, *pod;
    uint32_t *hx0, *hx1, *xt, *wt;
    cudaGetSymbolAddress((void**)&gi, g_gi);
    cudaGetSymbolAddress((void**)&xt, g_xt);
    cudaGetSymbolAddress((void**)&wt, g_wt);
    cudaGetSymbolAddress((void**)&h0, g_h0);
    cudaGetSymbolAddress((void**)&hx0, g_hx0);
    cudaGetSymbolAddress((void**)&hx1, g_hx1);
    cudaGetSymbolAddress((void**)&hall, g_hall);
    cudaGetSymbolAddress((void**)&Q2, g_Q2);
    cudaGetSymbolAddress((void**)&tmp, g_tmp);
    cudaGetSymbolAddress((void**)&WfullT, g_WfullT);
    cudaGetSymbolAddress((void**)&wvc, g_wvc);
    cudaGetSymbolAddress((void**)&vpd, g_vp);
    cudaGetSymbolAddress((void**)&pod, g_po);

    static int smem_set = 0;
    if (!smem_set) {
        cudaFuncSetAttribute(gru_persist, cudaFuncAttributeMaxDynamicSharedMemorySize,
                             GRU_SMEM_WORDS * 4);
        cudaFuncSetAttribute(gemm_xw, cudaFuncAttributeMaxDynamicSharedMemorySize,
                             XW_SMEM_WORDS * 4);
        smem_set = 1;
    }

    // 0: fused conv + init_h + wvc + barrier resets
    conv_all<<<CONVB + RALL + 1, 256>>>(node_input, ngh_input, Wih_node, Wih_ngh,
                                        node_hidden, ngh_hidden, Wprj, Wv,
                                        xt, wt, h0, hx0, wvc);

    // 1-2: input-side GEMMs
    gemm_xw<<<dim3(6, 32), 256, XW_SMEM_WORDS * 4>>>(xt, wt, gi);
    gemm_xw<<<dim3(6, 512), 256, XW_SMEM_WORDS * 4>>>(xt + (size_t)4096 * 128,
                                                      wt + 768 * 128,
                                                      gi + (size_t)4096 * 768);

    // 3: persistent recurrence + Wfull-chain helpers on idle SMs
    gru_persist<<<GRID_GRU, 256, GRU_SMEM_WORDS * 4>>>(gi, Whh_node, Whh_ngh,
                                                       bih_node, bhh_node, bih_ngh, bhh_ngh,
                                                       wvc, h0, hx0, hx1, out, hall, vpd,
                                                       Wq, Wbil, Wk, tmp, WfullT);

    // 4-6: attention + finalize
    sgemm_q2<<<dim3(2, 32), 256>>>(hall, WfullT, Q2);
    attn2_kernel<<<dim3(B_, 9), 256>>>(Q2, hall, vpd, bbil, out + OFF_A, pod);
    finalize<<<16, 256>>>(pod, bprj, out);
}